// round 2
// baseline (speedup 1.0000x reference)
#include <cuda_runtime.h>
#include <math.h>

#define Nn 1024
#define Bb 32
#define Ll 128
#define Hh 4
#define DE 16
#define KKp 4            // K+1
#define CC  512          // B * D_E columns

// ---------------- scratch (static device globals; no allocs allowed) ----------
__device__ float g_Abase[Nn * Nn];                 // 4 MB
__device__ float g_Q[Hh * Nn * DE];
__device__ float g_K[Hh * Nn * DE];
__device__ float g_Aeff[Hh * Nn * Nn];             // 16 MB
__device__ float g_G [Hh * KKp * Nn * CC];         // 32 MB : G[h][k][m][c], c=b*16+d
__device__ float g_P1[Hh * 3 * Nn * CC];           // A @ g_k, k=1..3
__device__ float g_P2[Hh * 2 * Nn * CC];           // A @ P1, k=2..3
__device__ float g_P3[Hh * Nn * CC];               // A @ P2, k=3

// ---------------- kernel 1: A_base = rowsoftmax(exp(-psi*dist2)) --------------
__global__ __launch_bounds__(256) void abase_kernel(const float* __restrict__ psi_emb,
                                                    const float* __restrict__ psi_s) {
    int i = blockIdx.x;
    int tid = threadIdx.x;
    __shared__ float sv[Nn];
    __shared__ float red[256];
    float pi[DE];
#pragma unroll
    for (int d = 0; d < DE; d++) pi[d] = psi_emb[i * DE + d];
    float psi = psi_s[0];

    float lmax = -1e30f;
    for (int j = tid; j < Nn; j += 256) {
        float s = 0.f;
#pragma unroll
        for (int d = 0; d < DE; d++) {
            float df = pi[d] - psi_emb[j * DE + d];
            s += df * df;
        }
        float v = expf(-psi * s);
        sv[j] = v;
        lmax = fmaxf(lmax, v);
    }
    red[tid] = lmax; __syncthreads();
    for (int s = 128; s > 0; s >>= 1) {
        if (tid < s) red[tid] = fmaxf(red[tid], red[tid + s]);
        __syncthreads();
    }
    float M = red[0]; __syncthreads();

    float lsum = 0.f;
    for (int j = tid; j < Nn; j += 256) {
        float e = expf(sv[j] - M);
        sv[j] = e;
        lsum += e;
    }
    red[tid] = lsum; __syncthreads();
    for (int s = 128; s > 0; s >>= 1) {
        if (tid < s) red[tid] += red[tid + s];
        __syncthreads();
    }
    float inv = 1.f / red[0];
    for (int j = tid; j < Nn; j += 256)
        g_Abase[i * Nn + j] = sv[j] * inv;
}

// ---------------- kernel 2: Q/K projections ----------------------------------
__global__ __launch_bounds__(256) void qk_kernel(const float* __restrict__ psi_emb,
                                                 const float* __restrict__ Wq,
                                                 const float* __restrict__ Wk) {
    int idx = blockIdx.x * 256 + threadIdx.x;          // over H*N*DE
    if (idx >= Hh * Nn * DE) return;
    int m = idx % DE;
    int n = (idx / DE) % Nn;
    int h = idx / (DE * Nn);
    float q = 0.f, k = 0.f;
#pragma unroll
    for (int d = 0; d < DE; d++) {
        float p = psi_emb[n * DE + d];
        q += p * Wq[(d * Hh + h) * DE + m];
        k += p * Wk[(d * Hh + h) * DE + m];
    }
    g_Q[(h * Nn + n) * DE + m] = q;
    g_K[(h * Nn + n) * DE + m] = k;
}

// ---------------- kernel 3: A_eff = a*A_base + (1-a)*softmax(QK^T/4) ----------
__global__ __launch_bounds__(256) void aeff_kernel(const float* __restrict__ attn_alpha) {
    int n = blockIdx.x;
    int h = blockIdx.y;
    int tid = threadIdx.x;
    __shared__ float sv[Nn];
    __shared__ float red[256];

    float qn[DE];
#pragma unroll
    for (int d = 0; d < DE; d++) qn[d] = g_Q[(h * Nn + n) * DE + d];

    const float scale = 0.25f;  // 1/sqrt(16)
    float lmax = -1e30f;
    for (int m = tid; m < Nn; m += 256) {
        const float4* kp = (const float4*)&g_K[(h * Nn + m) * DE];
        float s = 0.f;
#pragma unroll
        for (int q4 = 0; q4 < 4; q4++) {
            float4 kv = kp[q4];
            s += qn[q4 * 4 + 0] * kv.x + qn[q4 * 4 + 1] * kv.y +
                 qn[q4 * 4 + 2] * kv.z + qn[q4 * 4 + 3] * kv.w;
        }
        s *= scale;
        sv[m] = s;
        lmax = fmaxf(lmax, s);
    }
    red[tid] = lmax; __syncthreads();
    for (int s = 128; s > 0; s >>= 1) {
        if (tid < s) red[tid] = fmaxf(red[tid], red[tid + s]);
        __syncthreads();
    }
    float M = red[0]; __syncthreads();

    float lsum = 0.f;
    for (int m = tid; m < Nn; m += 256) {
        float e = expf(sv[m] - M);
        sv[m] = e;
        lsum += e;
    }
    red[tid] = lsum; __syncthreads();
    for (int s = 128; s > 0; s >>= 1) {
        if (tid < s) red[tid] += red[tid + s];
        __syncthreads();
    }
    float inv = 1.f / red[0];

    float a = attn_alpha[0];
    float alpha = 1.f / (1.f + expf(-a));
    float oma = 1.f - alpha;
    for (int m = tid; m < Nn; m += 256)
        g_Aeff[(h * Nn + n) * Nn + m] = alpha * g_Abase[n * Nn + m] + oma * sv[m] * inv;
}

// ---------------- kernel 4: G[h][k][m][b*16+d] = sum_l x[b,m,l] Fw[h,d,k,l] ---
// GEMM per b:  Xb(1024 x 128) @ Fmat^T(128 x 256) with scatter epilogue.
#define GBM 64
#define GBN 64
#define GBK 16
__global__ __launch_bounds__(256) void gemmG_kernel(const float* __restrict__ x,
                                                    const float* __restrict__ Fw) {
    int b  = blockIdx.z;
    int j0 = blockIdx.x * GBN;   // column block over j = (h*16+d)*4+k  (256 total)
    int m0 = blockIdx.y * GBM;   // row block over m
    int tid = threadIdx.x;
    int tx = tid % 16, ty = tid / 16;

    __shared__ float As[GBK][GBM];
    __shared__ float Bs[GBK][GBN];

    const float* Xb = x + b * Nn * Ll;

    int lar = tid / 4,  lac4 = (tid % 4) * 4;   // A load: 64 rows x 16 cols
    int lbr = tid / 4,  lbc4 = (tid % 4) * 4;   // B (Fmat) load: 64 j-rows x 16 l-cols

    float acc[4][4] = {};
    for (int kt = 0; kt < Ll; kt += GBK) {
        float4 av = *(const float4*)&Xb[(m0 + lar) * Ll + kt + lac4];
        As[lac4 + 0][lar] = av.x;  As[lac4 + 1][lar] = av.y;
        As[lac4 + 2][lar] = av.z;  As[lac4 + 3][lar] = av.w;
        float4 fv = *(const float4*)&Fw[(j0 + lbr) * Ll + kt + lbc4];
        Bs[lbc4 + 0][lbr] = fv.x;  Bs[lbc4 + 1][lbr] = fv.y;
        Bs[lbc4 + 2][lbr] = fv.z;  Bs[lbc4 + 3][lbr] = fv.w;
        __syncthreads();
#pragma unroll
        for (int l = 0; l < GBK; l++) {
            float4 a4 = *(const float4*)&As[l][ty * 4];
            float4 b4 = *(const float4*)&Bs[l][tx * 4];
            float ar[4] = {a4.x, a4.y, a4.z, a4.w};
            float br[4] = {b4.x, b4.y, b4.z, b4.w};
#pragma unroll
            for (int i = 0; i < 4; i++)
#pragma unroll
                for (int j = 0; j < 4; j++) acc[i][j] += ar[i] * br[j];
        }
        __syncthreads();
    }
#pragma unroll
    for (int i = 0; i < 4; i++) {
        int m = m0 + ty * 4 + i;
#pragma unroll
        for (int j = 0; j < 4; j++) {
            int jj = j0 + tx * 4 + j;
            int k = jj & 3, d = (jj >> 2) & 15, h = jj >> 6;
            g_G[((h * KKp + k) * Nn + m) * CC + b * DE + d] = acc[i][j];
        }
    }
}

// ---------------- kernel 5: batched SGEMM C = A_h(1024x1024) @ B(1024x512) ----
#define BM 64
#define BN 64
#define BKT 16
__global__ __launch_bounds__(256) void gemm_cheb(int level) {
    int z = blockIdx.z;
    const float* A; const float* Bm; float* Cm;
    if (level == 1) {
        int h = z / 3, ki = z % 3;
        A  = g_Aeff + h * Nn * Nn;
        Bm = g_G  + ((h * KKp) + (ki + 1)) * (Nn * CC);
        Cm = g_P1 + (h * 3 + ki) * (Nn * CC);
    } else if (level == 2) {
        int h = z / 2, t = z % 2;
        A  = g_Aeff + h * Nn * Nn;
        Bm = g_P1 + (h * 3 + t + 1) * (Nn * CC);
        Cm = g_P2 + (h * 2 + t) * (Nn * CC);
    } else {
        int h = z;
        A  = g_Aeff + h * Nn * Nn;
        Bm = g_P2 + (h * 2 + 1) * (Nn * CC);
        Cm = g_P3 + h * (Nn * CC);
    }

    __shared__ float As[BKT][BM];
    __shared__ float Bs[BKT][BN];
    int c0 = blockIdx.x * BN;
    int n0 = blockIdx.y * BM;
    int tid = threadIdx.x;
    int tx = tid % 16, ty = tid / 16;

    int lar = tid / 4,  lac4 = (tid % 4) * 4;   // A: 64 rows x 16 cols
    int lbr = tid / 16, lbc4 = (tid % 16) * 4;  // B: 16 rows x 64 cols

    float acc[4][4] = {};
    for (int kt = 0; kt < Nn; kt += BKT) {
        float4 av = *(const float4*)&A[(n0 + lar) * Nn + kt + lac4];
        As[lac4 + 0][lar] = av.x;  As[lac4 + 1][lar] = av.y;
        As[lac4 + 2][lar] = av.z;  As[lac4 + 3][lar] = av.w;
        *(float4*)&Bs[lbr][lbc4] = *(const float4*)&Bm[(kt + lbr) * CC + c0 + lbc4];
        __syncthreads();
#pragma unroll
        for (int l = 0; l < BKT; l++) {
            float4 a4 = *(const float4*)&As[l][ty * 4];
            float4 b4 = *(const float4*)&Bs[l][tx * 4];
            float ar[4] = {a4.x, a4.y, a4.z, a4.w};
            float br[4] = {b4.x, b4.y, b4.z, b4.w};
#pragma unroll
            for (int i = 0; i < 4; i++)
#pragma unroll
                for (int j = 0; j < 4; j++) acc[i][j] += ar[i] * br[j];
        }
        __syncthreads();
    }
#pragma unroll
    for (int i = 0; i < 4; i++) {
        float4 v = make_float4(acc[i][0], acc[i][1], acc[i][2], acc[i][3]);
        *(float4*)&Cm[(n0 + ty * 4 + i) * CC + c0 + tx * 4] = v;
    }
}

// ---------------- kernel 6: Chebyshev combine + psi contraction + head mix ----
__global__ __launch_bounds__(256) void final_kernel(const float* __restrict__ psi_emb,
                                                    const float* __restrict__ f_b,
                                                    const float* __restrict__ head_mix,
                                                    float* __restrict__ out) {
    int idx = blockIdx.x * 256 + threadIdx.x;   // n fastest for coalesced writes
    int n = idx & (Nn - 1);
    int b = idx >> 10;

    // softmax over head_mix (4 values)
    float hm[Hh];
    float mmax = -1e30f;
#pragma unroll
    for (int h = 0; h < Hh; h++) { hm[h] = head_mix[h]; mmax = fmaxf(mmax, hm[h]); }
    float msum = 0.f;
#pragma unroll
    for (int h = 0; h < Hh; h++) { hm[h] = expf(hm[h] - mmax); msum += hm[h]; }
    float minv = 1.f / msum;

    float pe[DE];
#pragma unroll
    for (int d = 0; d < DE; d++) pe[d] = psi_emb[n * DE + d];

    float acc = 0.f;
#pragma unroll
    for (int h = 0; h < Hh; h++) {
        float bf = 0.f;
#pragma unroll
        for (int d = 0; d < DE; d++) bf += pe[d] * f_b[h * DE + d];

        const float* G0  = g_G  + ((h * KKp + 0) * Nn + n) * CC + b * DE;
        const float* G2  = g_G  + ((h * KKp + 2) * Nn + n) * CC + b * DE;
        const float* P11 = g_P1 + ((h * 3 + 0) * Nn + n) * CC + b * DE;
        const float* P13 = g_P1 + ((h * 3 + 2) * Nn + n) * CC + b * DE;
        const float* P22 = g_P2 + ((h * 2 + 0) * Nn + n) * CC + b * DE;
        const float* P33 = g_P3 + (h * Nn + n) * CC + b * DE;

        float zacc = 0.f;
#pragma unroll
        for (int d = 0; d < DE; d++) {
            // Z = g0 + A g1 + 2 A^2 g2 - g2 + 4 A^3 g3 - 3 A g3
            float zval = G0[d] + P11[d] + 2.f * P22[d] - G2[d]
                       + 4.f * P33[d] - 3.f * P13[d];
            zacc += pe[d] * zval;
        }
        acc += hm[h] * minv * (zacc + bf);
    }
    out[b * Nn + n] = acc;
}

// ---------------- launcher ----------------------------------------------------
extern "C" void kernel_launch(void* const* d_in, const int* in_sizes, int n_in,
                              void* d_out, int out_size) {
    const float* x          = (const float*)d_in[0];
    const float* psi_emb    = (const float*)d_in[1];
    const float* psi        = (const float*)d_in[2];
    const float* Wq         = (const float*)d_in[3];
    const float* Wk         = (const float*)d_in[4];
    const float* attn_alpha = (const float*)d_in[5];
    const float* Fw         = (const float*)d_in[6];
    const float* fb         = (const float*)d_in[7];
    const float* hmix       = (const float*)d_in[8];
    float* out = (float*)d_out;

    abase_kernel<<<Nn, 256>>>(psi_emb, psi);
    qk_kernel<<<(Hh * Nn * DE + 255) / 256, 256>>>(psi_emb, Wq, Wk);
    aeff_kernel<<<dim3(Nn, Hh), 256>>>(attn_alpha);
    gemmG_kernel<<<dim3(4, Nn / GBM, Bb), 256>>>(x, Fw);
    gemm_cheb<<<dim3(CC / BN, Nn / BM, 12), 256>>>(1);
    gemm_cheb<<<dim3(CC / BN, Nn / BM,  8), 256>>>(2);
    gemm_cheb<<<dim3(CC / BN, Nn / BM,  4), 256>>>(3);
    final_kernel<<<(Bb * Nn) / 256, 256>>>(psi_emb, fb, hmix, out);
}